// round 1
// baseline (speedup 1.0000x reference)
#include <cuda_runtime.h>

// Problem constants: B=4, C=256, H=W=64, K=7, GROUPS=16, GC=16, CR=64
#define HW   4096
#define WDIM 64

typedef unsigned long long ull;

// Scratch for conv1 output x: [4][64][4096] fp32 = 4 MB (static device global, no allocs)
__device__ float g_xbuf[4 * 64 * 4096];

__device__ __forceinline__ ull pack2(float lo, float hi) {
    ull r;
    asm("mov.b64 %0, {%1, %2};" : "=l"(r) : "f"(lo), "f"(hi));
    return r;
}
__device__ __forceinline__ void unpack2(ull v, float &lo, float &hi) {
    asm("mov.b64 {%0, %1}, %2;" : "=f"(lo), "=f"(hi) : "l"(v));
}
// packed 2x fp32 FMA (Blackwell f32x2 pipe — 2x plain FFMA throughput)
__device__ __forceinline__ void fma2(ull &d, ull a, ull b) {
    asm("fma.rn.f32x2 %0, %1, %2, %0;" : "+l"(d) : "l"(a), "l"(b));
}

// ---------------------------------------------------------------------------
// Kernel 1: conv1 (1x1, 256->64) + BN(inference) + ReLU  ->  g_xbuf
// GEMM: x[b,m,p] = relu(bn(sum_r w1[m,r] * guide[b,r,p]))
// CTA: 64 m x 64 pixels, 256 threads, thread tile 4m x 4px (f32x2 over px pairs)
// ---------------------------------------------------------------------------
__global__ __launch_bounds__(256, 1)
void conv1_kernel(const float* __restrict__ guide,
                  const float* __restrict__ w1,
                  const float* __restrict__ gamma,
                  const float* __restrict__ beta,
                  const float* __restrict__ mean,
                  const float* __restrict__ var)
{
    __shared__ float w1t[64 * 68];  // [rr][m], stride 68
    __shared__ float gsh[64 * 68];  // [rr][px], stride 68

    const int tid   = threadIdx.x;
    const int b     = blockIdx.y;
    const int gpix0 = blockIdx.x * 64;
    const int mq = tid >> 4, pq = tid & 15;
    const int m0 = mq * 4,   p0 = pq * 4;

    ull acc[4][2];
    #pragma unroll
    for (int i = 0; i < 4; i++) { acc[i][0] = 0ull; acc[i][1] = 0ull; }

    for (int r0 = 0; r0 < 256; r0 += 64) {
        // stage w1 tile transposed: w1t[rr][m] = w1[m][r0+rr]
        #pragma unroll
        for (int i = tid; i < 4096; i += 256) {
            int m = i >> 6, rr = i & 63;
            w1t[rr * 68 + m] = w1[m * 256 + r0 + rr];
        }
        // stage guide tile: gsh[rr][px]
        #pragma unroll
        for (int i = tid; i < 1024; i += 256) {
            int rr = i >> 4, px4 = (i & 15) * 4;
            *(float4*)&gsh[rr * 68 + px4] =
                *(const float4*)&guide[(b * 256 + r0 + rr) * HW + gpix0 + px4];
        }
        __syncthreads();

        #pragma unroll 8
        for (int rr = 0; rr < 64; rr++) {
            float4 w4 = *(const float4*)&w1t[rr * 68 + m0];
            ulonglong2 xv = *(const ulonglong2*)&gsh[rr * 68 + p0];
            ull wp;
            wp = pack2(w4.x, w4.x); fma2(acc[0][0], xv.x, wp); fma2(acc[0][1], xv.y, wp);
            wp = pack2(w4.y, w4.y); fma2(acc[1][0], xv.x, wp); fma2(acc[1][1], xv.y, wp);
            wp = pack2(w4.z, w4.z); fma2(acc[2][0], xv.x, wp); fma2(acc[2][1], xv.y, wp);
            wp = pack2(w4.w, w4.w); fma2(acc[3][0], xv.x, wp); fma2(acc[3][1], xv.y, wp);
        }
        __syncthreads();
    }

    // epilogue: BN + ReLU, write x
    #pragma unroll
    for (int i = 0; i < 4; i++) {
        int m = m0 + i;
        float inv = gamma[m] * rsqrtf(var[m] + 1e-5f);
        float bsh = beta[m] - mean[m] * inv;
        float v0, v1, v2, v3;
        unpack2(acc[i][0], v0, v1);
        unpack2(acc[i][1], v2, v3);
        v0 = fmaxf(fmaf(v0, inv, bsh), 0.f);
        v1 = fmaxf(fmaf(v1, inv, bsh), 0.f);
        v2 = fmaxf(fmaf(v2, inv, bsh), 0.f);
        v3 = fmaxf(fmaf(v3, inv, bsh), 0.f);
        *(float4*)&g_xbuf[(b * 64 + m) * HW + gpix0 + p0] = make_float4(v0, v1, v2, v3);
    }
}

// ---------------------------------------------------------------------------
// Kernel 2: fused conv2 (per-pixel dynamic weights) + 7x7 dynamic aggregation
//           + residual. The 51 MB weight tensor never leaves SMEM.
// Grid: (group-quad 0..3, tile 0..15, b 0..3). CTA: 256 threads, 16x16 px tile,
// 4 groups per CTA. 160 KB dynamic smem, 1 CTA/SM.
// ---------------------------------------------------------------------------
__global__ __launch_bounds__(256, 1)
void fused_kernel(const float* __restrict__ feat,
                  const float* __restrict__ w2,
                  const float* __restrict__ b2,
                  float* __restrict__ out)
{
    extern __shared__ float smem[];
    float* x_sh   = smem;                 // [64][256]             65536 B
    float* f_sh   = x_sh + 64 * 256;      // [16][22][24]          33792 B
    float* w2_sh  = f_sh + 16 * 528;      // [64][56] ([r][kq*8+kk]) 14336 B
    float* wgt_sh = w2_sh + 64 * 56;      // [49][256]             50176 B

    const int tid  = threadIdx.x;
    const int gq   = blockIdx.x;              // group quad
    const int tile = blockIdx.y;
    const int b    = blockIdx.z;
    const int y0 = (tile >> 2) * 16;
    const int x0 = (tile & 3) * 16;

    // load x tile: x_sh[r][row*16+col]
    #pragma unroll 4
    for (int i = tid; i < 64 * 64; i += 256) {
        int r = i >> 6;
        int p4 = i & 63;
        int row = p4 >> 2, c4 = (p4 & 3) * 4;
        *(float4*)&x_sh[r * 256 + row * 16 + c4] =
            *(const float4*)&g_xbuf[(b * 64 + r) * HW + (y0 + row) * WDIM + x0 + c4];
    }

    // GEMM-phase thread mapping: warp = kq (7 k's each), lane = pq (8-px chunk)
    const int pq = tid & 31, kq = tid >> 5;
    // Agg-phase mapping: (cp 0..7, row 0..15, half 0..1) -> channels cp & cp+8, 8 px
    const int cp = tid >> 5, rowA = (tid >> 1) & 15, half = tid & 1;
    const int xbase = half * 8;

    for (int gi = 0; gi < 4; gi++) {
        const int g = gq * 4 + gi;

        // stage feature tile with 3-px halo, zero padded: f_sh[c][yy][xx]
        for (int i = tid; i < 16 * 484; i += 256) {
            int c = i / 484;
            int rem = i - c * 484;
            int yy = rem / 22;
            int xx = rem - yy * 22;
            int gy = y0 + yy - 3, gx = x0 + xx - 3;
            float v = 0.f;
            if ((unsigned)gy < 64u && (unsigned)gx < 64u)
                v = feat[(b * 256 + g * 16 + c) * HW + gy * WDIM + gx];
            f_sh[c * 528 + yy * 24 + xx] = v;
        }
        // stage w2 for this group, laid out [r][kq*8+kk] for float4 broadcast loads
        for (int i = tid; i < 49 * 64; i += 256) {
            int k = i >> 6, r = i & 63;
            int kqi = k / 7, kki = k - kqi * 7;
            w2_sh[r * 56 + kqi * 8 + kki] = w2[(g * 49 + k) * 64 + r];
        }
        __syncthreads();

        // -------- Phase 1: dynamic-weight GEMM  wgt[49][256] = w2_g @ x + b2
        if (kq < 7) {
            ull acc[7][4];
            #pragma unroll
            for (int kk = 0; kk < 7; kk++) {
                float bv = b2[g * 49 + kq * 7 + kk];
                ull bp = pack2(bv, bv);
                acc[kk][0] = bp; acc[kk][1] = bp; acc[kk][2] = bp; acc[kk][3] = bp;
            }
            const float* xp0 = &x_sh[pq * 8];
            const float* wp0 = &w2_sh[kq * 8];
            #pragma unroll 4
            for (int r = 0; r < 64; r++) {
                ulonglong2 xlo = *(const ulonglong2*)(xp0 + r * 256);
                ulonglong2 xhi = *(const ulonglong2*)(xp0 + r * 256 + 4);
                float wv[8];
                *(float4*)&wv[0] = *(const float4*)(wp0 + r * 56);
                *(float4*)&wv[4] = *(const float4*)(wp0 + r * 56 + 4);
                #pragma unroll
                for (int kk = 0; kk < 7; kk++) {
                    ull wpk = pack2(wv[kk], wv[kk]);
                    fma2(acc[kk][0], xlo.x, wpk);
                    fma2(acc[kk][1], xlo.y, wpk);
                    fma2(acc[kk][2], xhi.x, wpk);
                    fma2(acc[kk][3], xhi.y, wpk);
                }
            }
            #pragma unroll
            for (int kk = 0; kk < 7; kk++) {
                int k = kq * 7 + kk;
                ull* dst = (ull*)&wgt_sh[k * 256 + pq * 8];
                dst[0] = acc[kk][0]; dst[1] = acc[kk][1];
                dst[2] = acc[kk][2]; dst[3] = acc[kk][3];
            }
        }
        __syncthreads();

        // -------- Phase 2: 7x7 dynamic aggregation + residual
        {
            float acc0[8], acc1[8];
            #pragma unroll
            for (int j = 0; j < 8; j++) { acc0[j] = 0.f; acc1[j] = 0.f; }
            const int c0 = cp, c1 = cp + 8;

            #pragma unroll 1
            for (int di = 0; di < 7; di++) {
                float fr0[16], fr1[16];
                #pragma unroll
                for (int q = 0; q < 4; q++) {
                    *(float4*)&fr0[q * 4] =
                        *(const float4*)&f_sh[c0 * 528 + (rowA + di) * 24 + xbase + q * 4];
                    *(float4*)&fr1[q * 4] =
                        *(const float4*)&f_sh[c1 * 528 + (rowA + di) * 24 + xbase + q * 4];
                }
                #pragma unroll
                for (int dj = 0; dj < 7; dj++) {
                    int k = di * 7 + dj;
                    float wv[8];
                    *(float4*)&wv[0] = *(const float4*)&wgt_sh[k * 256 + rowA * 16 + xbase];
                    *(float4*)&wv[4] = *(const float4*)&wgt_sh[k * 256 + rowA * 16 + xbase + 4];
                    #pragma unroll
                    for (int j = 0; j < 8; j++) {
                        acc0[j] = fmaf(wv[j], fr0[j + dj], acc0[j]);
                        acc1[j] = fmaf(wv[j], fr1[j + dj], acc1[j]);
                    }
                }
            }
            // residual (feature at center = f_sh[...][row+3][x+3]) + store
            #pragma unroll
            for (int j = 0; j < 8; j++)
                acc0[j] += f_sh[c0 * 528 + (rowA + 3) * 24 + xbase + j + 3];
            #pragma unroll
            for (int j = 0; j < 8; j++)
                acc1[j] += f_sh[c1 * 528 + (rowA + 3) * 24 + xbase + j + 3];

            const int chbase = b * 256 + g * 16;
            float* op0 = &out[(chbase + c0) * HW + (y0 + rowA) * WDIM + x0 + xbase];
            *(float4*)(op0)     = make_float4(acc0[0], acc0[1], acc0[2], acc0[3]);
            *(float4*)(op0 + 4) = make_float4(acc0[4], acc0[5], acc0[6], acc0[7]);
            float* op1 = &out[(chbase + c1) * HW + (y0 + rowA) * WDIM + x0 + xbase];
            *(float4*)(op1)     = make_float4(acc1[0], acc1[1], acc1[2], acc1[3]);
            *(float4*)(op1 + 4) = make_float4(acc1[4], acc1[5], acc1[6], acc1[7]);
        }
        __syncthreads();  // protect f_sh/w2_sh/wgt_sh before next group's loads
    }
}

// ---------------------------------------------------------------------------
extern "C" void kernel_launch(void* const* d_in, const int* in_sizes, int n_in,
                              void* d_out, int out_size)
{
    const float* feat  = (const float*)d_in[0];
    const float* guide = (const float*)d_in[1];
    const float* w1    = (const float*)d_in[2];
    const float* gamma = (const float*)d_in[3];
    const float* beta  = (const float*)d_in[4];
    const float* mean  = (const float*)d_in[5];
    const float* var   = (const float*)d_in[6];
    const float* w2    = (const float*)d_in[7];
    const float* b2    = (const float*)d_in[8];
    float* out = (float*)d_out;

    conv1_kernel<<<dim3(64, 4), 256>>>(guide, w1, gamma, beta, mean, var);

    const int smem_bytes = (64 * 256 + 16 * 528 + 64 * 56 + 49 * 256) * 4;  // 163840
    cudaFuncSetAttribute(fused_kernel,
                         cudaFuncAttributeMaxDynamicSharedMemorySize, smem_bytes);
    fused_kernel<<<dim3(4, 16, 4), 256, smem_bytes>>>(feat, w2, b2, out);
}